// round 7
// baseline (speedup 1.0000x reference)
#include <cuda_runtime.h>

#define NN 64
#define CC 128
#define HH 64
#define WW 64
#define HID 8
#define NPLANE 9                       // 8 W_i2 rows + 1 bias plane

// Scratch (device globals). All fully rewritten every call -> deterministic.
__device__ float  g_gappart[NN][16][CC];   // per-chunk per-channel plane sums
__device__ float  g_ppart[NN][16][4];      // per-chunk per-wgroup sums (over c)
__device__ float  g_sp[NN][9];
__device__ float  g_co[NN][CC];
__device__ float  g_wz[NN][NPLANE];        // relu(h_j), j<8; [8]=1
__device__ float4 g_y[NPLANE][NN * 1024];  // 9 reduced planes (float4 quads)
__device__ float  g_z[NN][HH][WW];         // final weighted combination

// ---------------------------------------------------------------------------
// Kernel A': SINGLE pass over x (134 MB). Block = (chunk 0..15, n), 64 thr.
// Chunk covers 4 rows (256 pixels); thread t owns float4 quad q = chunk*64+t.
// Per channel c: accumulate 9 weighted planes (regs, input-independent
// weights W_i2/b_i2), per-thread running total (pool), warp-reduced
// per-channel partial (gap).
// ---------------------------------------------------------------------------
__global__ void kA_fused(const float* __restrict__ x,
                         const float* __restrict__ W_i2,
                         const float* __restrict__ b_i2) {
    int chunk = blockIdx.x;            // 0..15
    int n     = blockIdx.y;
    int t     = threadIdx.x;           // 0..63
    int warp  = t >> 5;
    int lane  = t & 31;

    __shared__ float sw[CC][12];       // [c][j] j<9, padded to 12 (16B align)
    __shared__ float sgpart[2][CC];
    __shared__ float stot[64];

    for (int idx = t; idx < CC * NPLANE; idx += 64) {
        int c = idx / NPLANE, j = idx - c * NPLANE;
        sw[c][j] = (j < 8) ? W_i2[j * CC + c] : b_i2[c];
    }
    __syncthreads();

    int q = chunk * 64 + t;            // float4 index within plane (0..1023)
    const float4* xp = (const float4*)x + (size_t)n * CC * 1024 + q;

    float4 acc[NPLANE];
#pragma unroll
    for (int j = 0; j < NPLANE; ++j) acc[j] = make_float4(0.f, 0.f, 0.f, 0.f);
    float tot = 0.f;

#pragma unroll 4
    for (int c = 0; c < CC; ++c) {
        float4 v  = xp[(size_t)c * 1024];
        float4 w0 = *(const float4*)&sw[c][0];
        float4 w1 = *(const float4*)&sw[c][4];
        float  w8 = sw[c][8];
        acc[0].x += w0.x * v.x; acc[0].y += w0.x * v.y; acc[0].z += w0.x * v.z; acc[0].w += w0.x * v.w;
        acc[1].x += w0.y * v.x; acc[1].y += w0.y * v.y; acc[1].z += w0.y * v.z; acc[1].w += w0.y * v.w;
        acc[2].x += w0.z * v.x; acc[2].y += w0.z * v.y; acc[2].z += w0.z * v.z; acc[2].w += w0.z * v.w;
        acc[3].x += w0.w * v.x; acc[3].y += w0.w * v.y; acc[3].z += w0.w * v.z; acc[3].w += w0.w * v.w;
        acc[4].x += w1.x * v.x; acc[4].y += w1.x * v.y; acc[4].z += w1.x * v.z; acc[4].w += w1.x * v.w;
        acc[5].x += w1.y * v.x; acc[5].y += w1.y * v.y; acc[5].z += w1.y * v.z; acc[5].w += w1.y * v.w;
        acc[6].x += w1.z * v.x; acc[6].y += w1.z * v.y; acc[6].z += w1.z * v.z; acc[6].w += w1.z * v.w;
        acc[7].x += w1.w * v.x; acc[7].y += w1.w * v.y; acc[7].z += w1.w * v.z; acc[7].w += w1.w * v.w;
        acc[8].x += w8   * v.x; acc[8].y += w8   * v.y; acc[8].z += w8   * v.z; acc[8].w += w8   * v.w;

        float s = (v.x + v.y) + (v.z + v.w);
        tot += s;
#pragma unroll
        for (int off = 16; off >= 1; off >>= 1)
            s += __shfl_xor_sync(0xFFFFFFFFu, s, off);
        if (lane == 0) sgpart[warp][c] = s;
    }

    // write the 9 reduced-plane quads
#pragma unroll
    for (int j = 0; j < NPLANE; ++j)
        g_y[j][n * 1024 + q] = acc[j];

    stot[t] = tot;
    __syncthreads();

    // gap partials: 128 channels over 64 threads
    for (int c = t; c < CC; c += 64)
        g_gappart[n][chunk][c] = sgpart[0][c] + sgpart[1][c];

    // pool partials: thread t -> local row r=t/16, quad qd=t%16, wgroup qd/4.
    // Threads 0..3 gather their wgroup's 16 entries (4 rows x 4 quads).
    if (t < 4) {
        float s = 0.f;
#pragma unroll
        for (int r = 0; r < 4; ++r)
#pragma unroll
            for (int k = 0; k < 4; ++k)
                s += stot[r * 16 + t * 4 + k];
        g_ppart[n][chunk][t] = s;
    }
}

// ---------------------------------------------------------------------------
// Kernel B: sum partials, run MLPs. One block per n, 128 threads.
// ---------------------------------------------------------------------------
__global__ void kB_mlp(const float* __restrict__ W_sp, const float* __restrict__ b_sp,
                       const float* __restrict__ W_o1, const float* __restrict__ b_o1,
                       const float* __restrict__ W_o2, const float* __restrict__ b_o2,
                       const float* __restrict__ W_i1, const float* __restrict__ b_i1) {
    int n = blockIdx.x;
    int t = threadIdx.x;               // 0..127

    __shared__ float sg[CC];
    __shared__ float sxs[16];
    __shared__ float sho[HID];

    {
        float s = 0.f;
#pragma unroll
        for (int k = 0; k < 16; ++k) s += g_gappart[n][k][t];
        sg[t] = s * (1.f / (HH * WW));
    }
    if (t < 16) {
        int hg = t >> 2, wg = t & 3;
        float s = 0.f;
#pragma unroll
        for (int k = 0; k < 4; ++k) s += g_ppart[n][hg * 4 + k][wg];
        sxs[t] = s * (1.f / (256.f * CC));
    }
    __syncthreads();

    if (t < HID) {
        float a = b_o1[t];
        float b = b_i1[t];
        for (int c = 0; c < CC; ++c) {
            a += sg[c] * W_o1[c * HID + t];
            b += sg[c] * W_i1[c * HID + t];
        }
        sho[t] = fmaxf(a, 0.f);
        g_wz[n][t] = fmaxf(b, 0.f);
    }
    if (t == HID) g_wz[n][8] = 1.f;    // bias-plane weight
    __syncthreads();

    float a = b_o2[t];
#pragma unroll
    for (int j = 0; j < HID; ++j)
        a += sho[j] * W_o2[j * CC + t];
    g_co[n][t] = a;

    if (t < 9) {
        float s = b_sp[t];
#pragma unroll
        for (int p = 0; p < 16; ++p) s += sxs[p] * W_sp[p * 9 + t];
        g_sp[n][t] = s;
    }
}

// ---------------------------------------------------------------------------
// Kernel Z: z = sum_j wz[j] * y_j. 256 blocks x 256 threads; L2-hot (9.4MB).
// ---------------------------------------------------------------------------
__global__ void kZ_combine(void) {
    int b = blockIdx.x;                // 0..255
    int t = threadIdx.x;               // 0..255
    int n = b >> 2;                    // 4 blocks per n
    int q = (b & 3) * 256 + t;         // quad 0..1023

    __shared__ float swz[NPLANE];
    if (t < NPLANE) swz[t] = g_wz[n][t];
    __syncthreads();

    float4 acc = make_float4(0.f, 0.f, 0.f, 0.f);
#pragma unroll
    for (int j = 0; j < NPLANE; ++j) {
        float4 v = g_y[j][n * 1024 + q];
        float s = swz[j];
        acc.x += s * v.x; acc.y += s * v.y;
        acc.z += s * v.z; acc.w += s * v.w;
    }
    ((float4*)g_z)[n * 1024 + q] = acc;
}

// ---------------------------------------------------------------------------
// Fused kernel DE: conv3x3 tile + 32-channel scaled store sweep.
// grid (8, NN, 4) = 2048 blocks, 256 threads. Streaming stores.
// ---------------------------------------------------------------------------
__global__ void kDE_convscale(float4* __restrict__ out) {
    int chunk = blockIdx.x;            // 0..7 -> output rows [chunk*8, +8)
    int n     = blockIdx.y;
    int ogrp  = blockIdx.z;            // 0..3 -> o in [ogrp*32, +32)
    int t     = threadIdx.x;           // 0..255

    __shared__ float sz[10][WW];
    __shared__ float st[8][WW];
    __shared__ float sco[32];
    __shared__ float ssp[9];

    int r0 = chunk * 8;

    if (t < 160) {
        int rr = t >> 4, qq = t & 15;
        int h = r0 - 1 + rr;
        float4 v = make_float4(0.f, 0.f, 0.f, 0.f);
        if (h >= 0 && h < HH)
            v = ((const float4*)g_z)[(n * HH + h) * 16 + qq];
        ((float4*)&sz[rr][0])[qq] = v;
    }
    if (t >= 192 && t < 224) sco[t - 192] = g_co[n][ogrp * 32 + (t - 192)];
    if (t >= 240 && t < 249) ssp[t - 240] = g_sp[n][t - 240];
    __syncthreads();

#pragma unroll
    for (int k = 0; k < 2; ++k) {
        int p = t + k * 256;           // 0..511
        int h = p >> 6, w = p & 63;
        float acc = 0.f;
#pragma unroll
        for (int kh = 0; kh < 3; ++kh) {
#pragma unroll
            for (int kw = 0; kw < 3; ++kw) {
                int ww = w + kw - 1;
                if (ww >= 0 && ww < WW)
                    acc += ssp[kh * 3 + kw] * sz[h + kh][ww];
            }
        }
        st[h][w] = acc;
    }
    __syncthreads();

    int q  = t & 127;
    int os = t >> 7;
    float4 v = ((const float4*)st)[q];
    int rr = q >> 4, qq = q & 15;

    int o0 = ogrp * 32 + os * 16;
    size_t base = ((size_t)n * CC + o0) * (HH * WW / 4)
                + (size_t)(r0 + rr) * 16 + qq;
#pragma unroll 4
    for (int o = 0; o < 16; ++o) {
        float s = sco[os * 16 + o];
        float4 ov;
        ov.x = v.x * s; ov.y = v.y * s; ov.z = v.z * s; ov.w = v.w * s;
        __stcs(&out[base + (size_t)o * (HH * WW / 4)], ov);
    }
}

// ---------------------------------------------------------------------------
extern "C" void kernel_launch(void* const* d_in, const int* in_sizes, int n_in,
                              void* d_out, int out_size) {
    const float* x    = (const float*)d_in[0];
    const float* W_sp = (const float*)d_in[1];
    const float* b_sp = (const float*)d_in[2];
    const float* W_o1 = (const float*)d_in[3];
    const float* b_o1 = (const float*)d_in[4];
    const float* W_o2 = (const float*)d_in[5];
    const float* b_o2 = (const float*)d_in[6];
    const float* W_i1 = (const float*)d_in[7];
    const float* b_i1 = (const float*)d_in[8];
    const float* W_i2 = (const float*)d_in[9];
    const float* b_i2 = (const float*)d_in[10];

    {
        dim3 g(16, NN);
        kA_fused<<<g, 64>>>(x, W_i2, b_i2);
    }
    kB_mlp<<<NN, CC>>>(W_sp, b_sp, W_o1, b_o1, W_o2, b_o2, W_i1, b_i1);
    kZ_combine<<<256, 256>>>();
    {
        dim3 g(8, NN, 4);
        kDE_convscale<<<g, 256>>>((float4*)d_out);
    }
}

// round 8
// speedup vs baseline: 1.4292x; 1.4292x over previous
#include <cuda_runtime.h>

#define NN 64
#define CC 128
#define HH 64
#define WW 64
#define HID 8
#define NPLANE 9                       // 8 W_i2 rows + 1 bias plane

// Scratch (device globals). All fully rewritten every call -> deterministic.
__device__ float  g_hpart[NN][16][16];     // per-chunk proj partials (o1|i1)
__device__ float  g_ppart[NN][16][4];      // per-chunk per-wgroup sums
__device__ float  g_sp[NN][9];
__device__ float  g_co[NN][CC];
__device__ float  g_wz[NN][NPLANE];        // relu(h_i[j]), j<8; [8]=1
__device__ float4 g_y[NPLANE][NN * 1024];  // 9 reduced planes (float4 quads)
__device__ float  g_z[NN][HH][WW];         // final weighted combination

// ---------------------------------------------------------------------------
// Kernel A': SINGLE pass over x (134 MB). Block = (chunk 0..15, n), 64 thr.
// Thread t owns float4 quad q = chunk*64+t. Inner loop over 128 channels is
// PURE LDG + broadcast-LDS + FMA (no shuffles/stores/branches) so loads
// software-pipeline. Accumulates:
//   - 9 weighted planes (W_i2 rows + bias)           -> g_y
//   - 16 scalar GAP projections (W_o1|W_i1 columns)  -> g_hpart (post-loop)
//   - per-thread pixel total                          -> g_ppart (pool)
// ---------------------------------------------------------------------------
__global__ void __launch_bounds__(64, 8)
kA_fused(const float* __restrict__ x,
         const float* __restrict__ W_i2, const float* __restrict__ b_i2,
         const float* __restrict__ W_o1, const float* __restrict__ W_i1) {
    int chunk = blockIdx.x;            // 0..15
    int n     = blockIdx.y;
    int t     = threadIdx.x;           // 0..63
    int warp  = t >> 5;
    int lane  = t & 31;

    __shared__ __align__(16) float swA[CC][12];  // [c][j]: 9 plane weights
    __shared__ __align__(16) float swB[CC][16];  // [c][j]: 16 proj weights
    __shared__ float stot[64];
    __shared__ float shp[2][16];

    for (int idx = t; idx < CC * NPLANE; idx += 64) {
        int c = idx / NPLANE, j = idx - c * NPLANE;
        swA[c][j] = (j < 8) ? W_i2[j * CC + c] : b_i2[c];
    }
    for (int idx = t; idx < CC * 16; idx += 64) {
        int c = idx >> 4, j = idx & 15;
        swB[c][j] = (j < 8) ? W_o1[c * HID + j] : W_i1[c * HID + (j - 8)];
    }
    __syncthreads();

    int q = chunk * 64 + t;            // float4 index within plane (0..1023)
    const float4* xp = (const float4*)x + (size_t)n * CC * 1024 + q;

    float4 acc[NPLANE];
#pragma unroll
    for (int j = 0; j < NPLANE; ++j) acc[j] = make_float4(0.f, 0.f, 0.f, 0.f);
    float hp[16];
#pragma unroll
    for (int j = 0; j < 16; ++j) hp[j] = 0.f;
    float tot = 0.f;

#pragma unroll 4
    for (int c = 0; c < CC; ++c) {
        float4 v  = xp[(size_t)c * 1024];
        float4 w0 = *(const float4*)&swA[c][0];
        float4 w1 = *(const float4*)&swA[c][4];
        float  w8 = swA[c][8];

        acc[0].x += w0.x * v.x; acc[0].y += w0.x * v.y; acc[0].z += w0.x * v.z; acc[0].w += w0.x * v.w;
        acc[1].x += w0.y * v.x; acc[1].y += w0.y * v.y; acc[1].z += w0.y * v.z; acc[1].w += w0.y * v.w;
        acc[2].x += w0.z * v.x; acc[2].y += w0.z * v.y; acc[2].z += w0.z * v.z; acc[2].w += w0.z * v.w;
        acc[3].x += w0.w * v.x; acc[3].y += w0.w * v.y; acc[3].z += w0.w * v.z; acc[3].w += w0.w * v.w;
        acc[4].x += w1.x * v.x; acc[4].y += w1.x * v.y; acc[4].z += w1.x * v.z; acc[4].w += w1.x * v.w;
        acc[5].x += w1.y * v.x; acc[5].y += w1.y * v.y; acc[5].z += w1.y * v.z; acc[5].w += w1.y * v.w;
        acc[6].x += w1.z * v.x; acc[6].y += w1.z * v.y; acc[6].z += w1.z * v.z; acc[6].w += w1.z * v.w;
        acc[7].x += w1.w * v.x; acc[7].y += w1.w * v.y; acc[7].z += w1.w * v.z; acc[7].w += w1.w * v.w;
        acc[8].x += w8   * v.x; acc[8].y += w8   * v.y; acc[8].z += w8   * v.z; acc[8].w += w8   * v.w;

        float s = (v.x + v.y) + (v.z + v.w);
        tot += s;

        float4 p0 = *(const float4*)&swB[c][0];
        float4 p1 = *(const float4*)&swB[c][4];
        float4 p2 = *(const float4*)&swB[c][8];
        float4 p3 = *(const float4*)&swB[c][12];
        hp[0]  += p0.x * s; hp[1]  += p0.y * s; hp[2]  += p0.z * s; hp[3]  += p0.w * s;
        hp[4]  += p1.x * s; hp[5]  += p1.y * s; hp[6]  += p1.z * s; hp[7]  += p1.w * s;
        hp[8]  += p2.x * s; hp[9]  += p2.y * s; hp[10] += p2.z * s; hp[11] += p2.w * s;
        hp[12] += p3.x * s; hp[13] += p3.y * s; hp[14] += p3.z * s; hp[15] += p3.w * s;
    }

    // write the 9 reduced-plane quads
#pragma unroll
    for (int j = 0; j < NPLANE; ++j)
        g_y[j][n * 1024 + q] = acc[j];

    // one-time warp reduce of the 16 projections, then cross-warp combine
#pragma unroll
    for (int j = 0; j < 16; ++j) {
        float s = hp[j];
#pragma unroll
        for (int off = 16; off >= 1; off >>= 1)
            s += __shfl_xor_sync(0xFFFFFFFFu, s, off);
        if (lane == 0) shp[warp][j] = s;
    }
    stot[t] = tot;
    __syncthreads();

    if (t < 16) g_hpart[n][chunk][t] = shp[0][t] + shp[1][t];

    // pool partials: thread t -> local row r=t/16, quad qd=t%16, wgroup qd/4.
    if (t < 4) {
        float s = 0.f;
#pragma unroll
        for (int r = 0; r < 4; ++r)
#pragma unroll
            for (int k = 0; k < 4; ++k)
                s += stot[r * 16 + t * 4 + k];
        g_ppart[n][chunk][t] = s;
    }
}

// ---------------------------------------------------------------------------
// Kernel B: fold partials, finish MLPs. One block per n, 128 threads.
// ---------------------------------------------------------------------------
__global__ void kB_mlp(const float* __restrict__ W_sp, const float* __restrict__ b_sp,
                       const float* __restrict__ b_o1, const float* __restrict__ b_i1,
                       const float* __restrict__ W_o2, const float* __restrict__ b_o2) {
    int n = blockIdx.x;
    int t = threadIdx.x;               // 0..127

    __shared__ float sho[HID];
    __shared__ float sxs[16];

    if (t < 16) {
        float s = 0.f;
#pragma unroll
        for (int k = 0; k < 16; ++k) s += g_hpart[n][k][t];
        s *= (1.f / (CC * 32.f));      // 1/4096 = 1/(H*W)
        if (t < 8) sho[t] = fmaxf(s + b_o1[t], 0.f);
        else       g_wz[n][t - 8] = fmaxf(s + b_i1[t - 8], 0.f);
    }
    if (t == 16) g_wz[n][8] = 1.f;     // bias-plane weight
    if (t >= 32 && t < 48) {           // pooled xs
        int p = t - 32;
        int hg = p >> 2, wg = p & 3;
        float s = 0.f;
#pragma unroll
        for (int k = 0; k < 4; ++k) s += g_ppart[n][hg * 4 + k][wg];
        sxs[p] = s * (1.f / (256.f * CC));
    }
    __syncthreads();

    float a = b_o2[t];
#pragma unroll
    for (int j = 0; j < HID; ++j)
        a += sho[j] * W_o2[j * CC + t];
    g_co[n][t] = a;

    if (t < 9) {
        float s = b_sp[t];
#pragma unroll
        for (int p = 0; p < 16; ++p) s += sxs[p] * W_sp[p * 9 + t];
        g_sp[n][t] = s;
    }
}

// ---------------------------------------------------------------------------
// Kernel Z: z = sum_j wz[j] * y_j. 256 blocks x 256 threads; L2-hot (9.4MB).
// ---------------------------------------------------------------------------
__global__ void kZ_combine(void) {
    int b = blockIdx.x;                // 0..255
    int t = threadIdx.x;               // 0..255
    int n = b >> 2;                    // 4 blocks per n
    int q = (b & 3) * 256 + t;         // quad 0..1023

    __shared__ float swz[NPLANE];
    if (t < NPLANE) swz[t] = g_wz[n][t];
    __syncthreads();

    float4 acc = make_float4(0.f, 0.f, 0.f, 0.f);
#pragma unroll
    for (int j = 0; j < NPLANE; ++j) {
        float4 v = g_y[j][n * 1024 + q];
        float s = swz[j];
        acc.x += s * v.x; acc.y += s * v.y;
        acc.z += s * v.z; acc.w += s * v.w;
    }
    ((float4*)g_z)[n * 1024 + q] = acc;
}

// ---------------------------------------------------------------------------
// Fused kernel DE: conv3x3 tile + 32-channel scaled store sweep.
// grid (8, NN, 4) = 2048 blocks, 256 threads. Streaming stores.
// ---------------------------------------------------------------------------
__global__ void kDE_convscale(float4* __restrict__ out) {
    int chunk = blockIdx.x;            // 0..7 -> output rows [chunk*8, +8)
    int n     = blockIdx.y;
    int ogrp  = blockIdx.z;            // 0..3 -> o in [ogrp*32, +32)
    int t     = threadIdx.x;           // 0..255

    __shared__ float sz[10][WW];
    __shared__ float st[8][WW];
    __shared__ float sco[32];
    __shared__ float ssp[9];

    int r0 = chunk * 8;

    if (t < 160) {
        int rr = t >> 4, qq = t & 15;
        int h = r0 - 1 + rr;
        float4 v = make_float4(0.f, 0.f, 0.f, 0.f);
        if (h >= 0 && h < HH)
            v = ((const float4*)g_z)[(n * HH + h) * 16 + qq];
        ((float4*)&sz[rr][0])[qq] = v;
    }
    if (t >= 192 && t < 224) sco[t - 192] = g_co[n][ogrp * 32 + (t - 192)];
    if (t >= 240 && t < 249) ssp[t - 240] = g_sp[n][t - 240];
    __syncthreads();

#pragma unroll
    for (int k = 0; k < 2; ++k) {
        int p = t + k * 256;           // 0..511
        int h = p >> 6, w = p & 63;
        float acc = 0.f;
#pragma unroll
        for (int kh = 0; kh < 3; ++kh) {
#pragma unroll
            for (int kw = 0; kw < 3; ++kw) {
                int ww = w + kw - 1;
                if (ww >= 0 && ww < WW)
                    acc += ssp[kh * 3 + kw] * sz[h + kh][ww];
            }
        }
        st[h][w] = acc;
    }
    __syncthreads();

    int q  = t & 127;
    int os = t >> 7;
    float4 v = ((const float4*)st)[q];
    int rr = q >> 4, qq = q & 15;

    int o0 = ogrp * 32 + os * 16;
    size_t base = ((size_t)n * CC + o0) * (HH * WW / 4)
                + (size_t)(r0 + rr) * 16 + qq;
#pragma unroll 4
    for (int o = 0; o < 16; ++o) {
        float s = sco[os * 16 + o];
        float4 ov;
        ov.x = v.x * s; ov.y = v.y * s; ov.z = v.z * s; ov.w = v.w * s;
        __stcs(&out[base + (size_t)o * (HH * WW / 4)], ov);
    }
}

// ---------------------------------------------------------------------------
extern "C" void kernel_launch(void* const* d_in, const int* in_sizes, int n_in,
                              void* d_out, int out_size) {
    const float* x    = (const float*)d_in[0];
    const float* W_sp = (const float*)d_in[1];
    const float* b_sp = (const float*)d_in[2];
    const float* W_o1 = (const float*)d_in[3];
    const float* b_o1 = (const float*)d_in[4];
    const float* W_o2 = (const float*)d_in[5];
    const float* b_o2 = (const float*)d_in[6];
    const float* W_i1 = (const float*)d_in[7];
    const float* b_i1 = (const float*)d_in[8];
    const float* W_i2 = (const float*)d_in[9];
    const float* b_i2 = (const float*)d_in[10];

    {
        dim3 g(16, NN);
        kA_fused<<<g, 64>>>(x, W_i2, b_i2, W_o1, W_i1);
    }
    kB_mlp<<<NN, CC>>>(W_sp, b_sp, b_o1, b_i1, W_o2, b_o2);
    kZ_combine<<<256, 256>>>();
    {
        dim3 g(8, NN, 4);
        kDE_convscale<<<g, 256>>>((float4*)d_out);
    }
}

// round 9
// speedup vs baseline: 1.4297x; 1.0004x over previous
#include <cuda_runtime.h>

#define NN 64
#define CC 128
#define HH 64
#define WW 64
#define HID 8
#define NPLANE 9                       // 8 W_i2 rows + 1 bias plane

typedef unsigned long long u64;

// Packed fp32x2 ops (Blackwell FFMA2 — PTX-only, ptxas never auto-fuses)
#define F32X2_FMA(d, a, b, c) \
    asm("fma.rn.f32x2 %0, %1, %2, %3;" : "=l"(d) : "l"(a), "l"(b), "l"(c))
#define F32X2_ADD(d, a, b) \
    asm("add.rn.f32x2 %0, %1, %2;" : "=l"(d) : "l"(a), "l"(b))
#define F32X2_PACK(d, lo, hi) \
    asm("mov.b64 %0, {%1, %2};" : "=l"(d) : "f"(lo), "f"(hi))
#define F32X2_UNPACK(lo, hi, s) \
    asm("mov.b64 {%0, %1}, %2;" : "=f"(lo), "=f"(hi) : "l"(s))

// Scratch (device globals). All fully rewritten every call -> deterministic.
__device__ float  g_hpart[NN][16][16];     // per-chunk proj partials (o1|i1)
__device__ float  g_ppart[NN][16][4];      // per-chunk per-wgroup sums
__device__ float  g_sp[NN][9];
__device__ float  g_co[NN][CC];
__device__ float  g_wz[NN][NPLANE];        // relu(h_i[j]), j<8; [8]=1
__device__ float4 g_y[NPLANE][NN * 1024];  // 9 reduced planes (float4 quads)
__device__ float  g_z[NN][HH][WW];         // final weighted combination

// ---------------------------------------------------------------------------
// Kernel A': SINGLE pass over x (134 MB), inner loop in packed f32x2.
// Block = (chunk 0..15, n), 64 threads; thread owns quad q = chunk*64+t.
// Per channel: 18 FFMA2 (9 planes) + 8 FFMA2 (16 gap projections) +
// 1 ADD2 + 2 scalar — half the fma-pipe cost of the scalar version.
// ---------------------------------------------------------------------------
__global__ void __launch_bounds__(64, 8)
kA_fused(const float* __restrict__ x,
         const float* __restrict__ W_i2, const float* __restrict__ b_i2,
         const float* __restrict__ W_o1, const float* __restrict__ W_i1) {
    int chunk = blockIdx.x;            // 0..15
    int n     = blockIdx.y;
    int t     = threadIdx.x;           // 0..63
    int warp  = t >> 5;
    int lane  = t & 31;

    __shared__ __align__(16) u64   swA2[CC][12]; // [c][j]: (w,w) pairs, j<9
    __shared__ __align__(16) float swB[CC][16];  // [c][j]: 16 proj weights
    __shared__ float stot[64];
    __shared__ float shp[2][16];

    for (int idx = t; idx < CC * NPLANE; idx += 64) {
        int c = idx / NPLANE, j = idx - c * NPLANE;
        float w = (j < 8) ? W_i2[j * CC + c] : b_i2[c];
        u64 ww; F32X2_PACK(ww, w, w);
        swA2[c][j] = ww;
    }
    for (int idx = t; idx < CC * 16; idx += 64) {
        int c = idx >> 4, j = idx & 15;
        swB[c][j] = (j < 8) ? W_o1[c * HID + j] : W_i1[c * HID + (j - 8)];
    }
    __syncthreads();

    int q = chunk * 64 + t;            // float4 index within plane (0..1023)
    const float4* xp = (const float4*)x + (size_t)n * CC * 1024 + q;

    u64 acc[2 * NPLANE];               // [2j]=lanes(x,y), [2j+1]=lanes(z,w)
#pragma unroll
    for (int j = 0; j < 2 * NPLANE; ++j) acc[j] = 0ull;
    u64 hp2[8];
#pragma unroll
    for (int j = 0; j < 8; ++j) hp2[j] = 0ull;
    float tot = 0.f;

#pragma unroll 4
    for (int c = 0; c < CC; ++c) {
        float4 v = xp[(size_t)c * 1024];
        u64 vlo, vhi;
        F32X2_PACK(vlo, v.x, v.y);
        F32X2_PACK(vhi, v.z, v.w);

        const u64* wa = &swA2[c][0];
#pragma unroll
        for (int j = 0; j < NPLANE; ++j) {
            u64 w = wa[j];
            F32X2_FMA(acc[2 * j],     w, vlo, acc[2 * j]);
            F32X2_FMA(acc[2 * j + 1], w, vhi, acc[2 * j + 1]);
        }

        u64 sv; F32X2_ADD(sv, vlo, vhi);
        float s0, s1; F32X2_UNPACK(s0, s1, sv);
        float s = s0 + s1;
        tot += s;
        u64 s2; F32X2_PACK(s2, s, s);

        const u64* pb = (const u64*)&swB[c][0];
#pragma unroll
        for (int k = 0; k < 8; ++k)
            F32X2_FMA(hp2[k], pb[k], s2, hp2[k]);
    }

    // write the 9 reduced-plane quads
#pragma unroll
    for (int j = 0; j < NPLANE; ++j) {
        float a0, a1, a2, a3;
        F32X2_UNPACK(a0, a1, acc[2 * j]);
        F32X2_UNPACK(a2, a3, acc[2 * j + 1]);
        g_y[j][n * 1024 + q] = make_float4(a0, a1, a2, a3);
    }

    // one-time warp reduce of the 16 projections, then cross-warp combine
#pragma unroll
    for (int k = 0; k < 8; ++k) {
        float h0, h1; F32X2_UNPACK(h0, h1, hp2[k]);
#pragma unroll
        for (int off = 16; off >= 1; off >>= 1) {
            h0 += __shfl_xor_sync(0xFFFFFFFFu, h0, off);
            h1 += __shfl_xor_sync(0xFFFFFFFFu, h1, off);
        }
        if (lane == 0) { shp[warp][2 * k] = h0; shp[warp][2 * k + 1] = h1; }
    }
    stot[t] = tot;
    __syncthreads();

    if (t < 16) g_hpart[n][chunk][t] = shp[0][t] + shp[1][t];

    // pool partials: thread t -> local row r=t/16, quad qd=t%16, wgroup qd/4.
    if (t < 4) {
        float s = 0.f;
#pragma unroll
        for (int r = 0; r < 4; ++r)
#pragma unroll
            for (int k = 0; k < 4; ++k)
                s += stot[r * 16 + t * 4 + k];
        g_ppart[n][chunk][t] = s;
    }
}

// ---------------------------------------------------------------------------
// Kernel B: fold partials, finish MLPs. One block per n, 128 threads.
// ---------------------------------------------------------------------------
__global__ void kB_mlp(const float* __restrict__ W_sp, const float* __restrict__ b_sp,
                       const float* __restrict__ b_o1, const float* __restrict__ b_i1,
                       const float* __restrict__ W_o2, const float* __restrict__ b_o2) {
    int n = blockIdx.x;
    int t = threadIdx.x;               // 0..127

    __shared__ float sho[HID];
    __shared__ float sxs[16];

    if (t < 16) {
        float s = 0.f;
#pragma unroll
        for (int k = 0; k < 16; ++k) s += g_hpart[n][k][t];
        s *= (1.f / (CC * 32.f));      // 1/4096 = 1/(H*W)
        if (t < 8) sho[t] = fmaxf(s + b_o1[t], 0.f);
        else       g_wz[n][t - 8] = fmaxf(s + b_i1[t - 8], 0.f);
    }
    if (t == 16) g_wz[n][8] = 1.f;     // bias-plane weight
    if (t >= 32 && t < 48) {           // pooled xs
        int p = t - 32;
        int hg = p >> 2, wg = p & 3;
        float s = 0.f;
#pragma unroll
        for (int k = 0; k < 4; ++k) s += g_ppart[n][hg * 4 + k][wg];
        sxs[p] = s * (1.f / (256.f * CC));
    }
    __syncthreads();

    float a = b_o2[t];
#pragma unroll
    for (int j = 0; j < HID; ++j)
        a += sho[j] * W_o2[j * CC + t];
    g_co[n][t] = a;

    if (t < 9) {
        float s = b_sp[t];
#pragma unroll
        for (int p = 0; p < 16; ++p) s += sxs[p] * W_sp[p * 9 + t];
        g_sp[n][t] = s;
    }
}

// ---------------------------------------------------------------------------
// Kernel Z: z = sum_j wz[j] * y_j. 256 blocks x 256 threads; L2-hot (9.4MB).
// ---------------------------------------------------------------------------
__global__ void kZ_combine(void) {
    int b = blockIdx.x;                // 0..255
    int t = threadIdx.x;               // 0..255
    int n = b >> 2;                    // 4 blocks per n
    int q = (b & 3) * 256 + t;         // quad 0..1023

    __shared__ float swz[NPLANE];
    if (t < NPLANE) swz[t] = g_wz[n][t];
    __syncthreads();

    float4 acc = make_float4(0.f, 0.f, 0.f, 0.f);
#pragma unroll
    for (int j = 0; j < NPLANE; ++j) {
        float4 v = g_y[j][n * 1024 + q];
        float s = swz[j];
        acc.x += s * v.x; acc.y += s * v.y;
        acc.z += s * v.z; acc.w += s * v.w;
    }
    ((float4*)g_z)[n * 1024 + q] = acc;
}

// ---------------------------------------------------------------------------
// Fused kernel DE: conv3x3 tile + 32-channel scaled store sweep.
// grid (8, NN, 4) = 2048 blocks, 256 threads. Streaming stores.
// ---------------------------------------------------------------------------
__global__ void kDE_convscale(float4* __restrict__ out) {
    int chunk = blockIdx.x;            // 0..7 -> output rows [chunk*8, +8)
    int n     = blockIdx.y;
    int ogrp  = blockIdx.z;            // 0..3 -> o in [ogrp*32, +32)
    int t     = threadIdx.x;           // 0..255

    __shared__ float sz[10][WW];
    __shared__ float st[8][WW];
    __shared__ float sco[32];
    __shared__ float ssp[9];

    int r0 = chunk * 8;

    if (t < 160) {
        int rr = t >> 4, qq = t & 15;
        int h = r0 - 1 + rr;
        float4 v = make_float4(0.f, 0.f, 0.f, 0.f);
        if (h >= 0 && h < HH)
            v = ((const float4*)g_z)[(n * HH + h) * 16 + qq];
        ((float4*)&sz[rr][0])[qq] = v;
    }
    if (t >= 192 && t < 224) sco[t - 192] = g_co[n][ogrp * 32 + (t - 192)];
    if (t >= 240 && t < 249) ssp[t - 240] = g_sp[n][t - 240];
    __syncthreads();

#pragma unroll
    for (int k = 0; k < 2; ++k) {
        int p = t + k * 256;           // 0..511
        int h = p >> 6, w = p & 63;
        float acc = 0.f;
#pragma unroll
        for (int kh = 0; kh < 3; ++kh) {
#pragma unroll
            for (int kw = 0; kw < 3; ++kw) {
                int ww = w + kw - 1;
                if (ww >= 0 && ww < WW)
                    acc += ssp[kh * 3 + kw] * sz[h + kh][ww];
            }
        }
        st[h][w] = acc;
    }
    __syncthreads();

    int q  = t & 127;
    int os = t >> 7;
    float4 v = ((const float4*)st)[q];
    int rr = q >> 4, qq = q & 15;

    int o0 = ogrp * 32 + os * 16;
    size_t base = ((size_t)n * CC + o0) * (HH * WW / 4)
                + (size_t)(r0 + rr) * 16 + qq;
#pragma unroll 4
    for (int o = 0; o < 16; ++o) {
        float s = sco[os * 16 + o];
        float4 ov;
        ov.x = v.x * s; ov.y = v.y * s; ov.z = v.z * s; ov.w = v.w * s;
        __stcs(&out[base + (size_t)o * (HH * WW / 4)], ov);
    }
}

// ---------------------------------------------------------------------------
extern "C" void kernel_launch(void* const* d_in, const int* in_sizes, int n_in,
                              void* d_out, int out_size) {
    const float* x    = (const float*)d_in[0];
    const float* W_sp = (const float*)d_in[1];
    const float* b_sp = (const float*)d_in[2];
    const float* W_o1 = (const float*)d_in[3];
    const float* b_o1 = (const float*)d_in[4];
    const float* W_o2 = (const float*)d_in[5];
    const float* b_o2 = (const float*)d_in[6];
    const float* W_i1 = (const float*)d_in[7];
    const float* b_i1 = (const float*)d_in[8];
    const float* W_i2 = (const float*)d_in[9];
    const float* b_i2 = (const float*)d_in[10];

    {
        dim3 g(16, NN);
        kA_fused<<<g, 64>>>(x, W_i2, b_i2, W_o1, W_i1);
    }
    kB_mlp<<<NN, CC>>>(W_sp, b_sp, b_o1, b_i1, W_o2, b_o2);
    kZ_combine<<<256, 256>>>();
    {
        dim3 g(8, NN, 4);
        kDE_convscale<<<g, 256>>>((float4*)d_out);
    }
}